// round 7
// baseline (speedup 1.0000x reference)
#include <cuda_runtime.h>
#include <cuda_bf16.h>
#include <cstdint>

#define BATCH    32768
#define IN_DIM   256
#define HID      512
#define OUT_DIM  128
#define NSTEPS   40
#define DT       0.025f
#define HDT      0.0125f
#define DT6      (0.025f / 6.0f)

// ---------------- static device scratch ----------------
__device__ __align__(128) __nv_bfloat16 g_S0h[(size_t)BATCH * HID];
__device__ __align__(128) __nv_bfloat16 g_S0l[(size_t)BATCH * HID];
__device__ __align__(128) __nv_bfloat16 g_S1h[(size_t)BATCH * HID];
__device__ __align__(128) __nv_bfloat16 g_S1l[(size_t)BATCH * HID];
__device__ __align__(128) __nv_bfloat16 g_S2h[(size_t)BATCH * HID];
__device__ __align__(128) __nv_bfloat16 g_S2l[(size_t)BATCH * HID];
__device__ __align__(128) __nv_bfloat16 g_S3h[(size_t)BATCH * HID];
__device__ __align__(128) __nv_bfloat16 g_S3l[(size_t)BATCH * HID];
__device__ __align__(128) __nv_bfloat16 g_Wbig[(size_t)HID * 1536];  // [n][k']: Whi|Whi|Wlo
__device__ __align__(128) __nv_bfloat16 g_Ubig[(size_t)HID * 1536];  // [n][k']: Uhi|Uhi|Ulo
__device__ __align__(128) float g_drive[(size_t)BATCH * HID];
__device__ __align__(128) float g_itau[HID];

__device__ __forceinline__ __nv_bfloat16* Sh_ptr(int i) {
  switch (i) { case 0: return g_S0h; case 1: return g_S1h; case 2: return g_S2h; default: return g_S3h; }
}
__device__ __forceinline__ __nv_bfloat16* Sl_ptr(int i) {
  switch (i) { case 0: return g_S0l; case 1: return g_S1l; case 2: return g_S2l; default: return g_S3l; }
}

// ---------------- helpers ----------------
__device__ __forceinline__ uint32_t smem_u32(const void* p) {
  uint32_t a;
  asm("{ .reg .u64 t; cvta.to.shared.u64 t, %1; cvt.u32.u64 %0, t; }" : "=r"(a) : "l"(p));
  return a;
}
__device__ __forceinline__ void cp16(uint32_t dst, const void* src) {
  asm volatile("cp.async.cg.shared.global [%0], [%1], 16;" :: "r"(dst), "l"(src) : "memory");
}
#define CP_COMMIT() asm volatile("cp.async.commit_group;" ::: "memory")
#define CP_WAIT1()  asm volatile("cp.async.wait_group 1;" ::: "memory")

#define LDSM4(r0, r1, r2, r3, a) \
  asm volatile("ldmatrix.sync.aligned.m8n8.x4.shared.b16 {%0,%1,%2,%3}, [%4];" \
               : "=r"(r0), "=r"(r1), "=r"(r2), "=r"(r3) : "r"(a))

#define MMA16816(d, a, b0, b1) \
  asm volatile("mma.sync.aligned.m16n8k16.row.col.f32.bf16.bf16.f32 " \
               "{%0,%1,%2,%3},{%4,%5,%6,%7},{%8,%9},{%0,%1,%2,%3};" \
               : "+f"((d)[0]), "+f"((d)[1]), "+f"((d)[2]), "+f"((d)[3]) \
               : "r"((a)[0]), "r"((a)[1]), "r"((a)[2]), "r"((a)[3]), "r"(b0), "r"(b1))

__device__ __forceinline__ float tanh_fast(float x) {
  float e = __expf(2.0f * x);
  return 1.0f - __fdividef(2.0f, e + 1.0f);
}

// ---------------- prep: W/U -> [hi | hi | lo] bf16, itau ----------------
__global__ void k_prep(const float* __restrict__ W, const float* __restrict__ U,
                       const float* __restrict__ tau) {
  int idx = blockIdx.x * 256 + threadIdx.x;           // 2*512*1536 total
  const int HALF = 512 * 1536;
  int h = (idx >= HALF) ? 1 : 0;
  int j = idx - h * HALF;
  int n = j / 1536, k = j % 1536;
  int kk = k & 511, region = k >> 9;
  const float* src = h ? U : W;
  __nv_bfloat16* dst = h ? g_Ubig : g_Wbig;
  float w = src[n * 512 + kk];
  __nv_bfloat16 hi = __float2bfloat16(w);
  dst[j] = (region < 2) ? hi : __float2bfloat16(w - __bfloat162float(hi));
  if (idx < HID) g_itau[idx] = 1.0f / tau[idx];
}

// ---------------- fp32 microtile GEMM (k_in / k_head) ----------------
template <int K>
__device__ __forceinline__ void gemm_tile(const float* __restrict__ As,
                                          const float* __restrict__ Bg,
                                          int row0, int col0, float acc[4][16]) {
#pragma unroll
  for (int i = 0; i < 4; i++)
#pragma unroll
    for (int j = 0; j < 16; j++) acc[i][j] = 0.f;
#pragma unroll 1
  for (int k = 0; k < K; k += 4) {
    float4 a[4];
#pragma unroll
    for (int kk = 0; kk < 4; kk++)
      a[kk] = *reinterpret_cast<const float4*>(As + (k + kk) * 32 + row0);
    float4 bb[16];
#pragma unroll
    for (int j = 0; j < 16; j++)
      bb[j] = *reinterpret_cast<const float4*>(Bg + (size_t)(col0 + j) * K + k);
#pragma unroll
    for (int j = 0; j < 16; j++) {
      float bv[4] = {bb[j].x, bb[j].y, bb[j].z, bb[j].w};
#pragma unroll
      for (int kk = 0; kk < 4; kk++) {
        acc[0][j] = fmaf(a[kk].x, bv[kk], acc[0][j]);
        acc[1][j] = fmaf(a[kk].y, bv[kk], acc[1][j]);
        acc[2][j] = fmaf(a[kk].z, bv[kk], acc[2][j]);
        acc[3][j] = fmaf(a[kk].w, bv[kk], acc[3][j]);
      }
    }
  }
}

// u = x @ Wx^T + bx ; writes S0 (h0 = u) as bf16 hi/lo
__global__ void __launch_bounds__(256, 1)
k_in(const float* __restrict__ x, const float* __restrict__ Wx,
     const float* __restrict__ bx) {
  extern __shared__ float sm[];
  const int tid = threadIdx.x, b0 = blockIdx.x * 32;
  for (int idx = tid; idx < 32 * IN_DIM; idx += 256) {
    int m = idx >> 8, k = idx & 255;
    sm[k * 32 + m] = x[(size_t)(b0 + m) * IN_DIM + k];
  }
  __syncthreads();
  const int row0 = (tid & 7) * 4, col0 = (tid >> 3) * 16;
  float acc[4][16];
  gemm_tile<IN_DIM>(sm, Wx, row0, col0, acc);
#pragma unroll
  for (int j = 0; j < 16; j++) {
    float bxi = bx[col0 + j];
#pragma unroll
    for (int i = 0; i < 4; i++) {
      float v = acc[i][j] + bxi;
      size_t ix = (size_t)(b0 + row0 + i) * HID + col0 + j;
      __nv_bfloat16 hi = __float2bfloat16(v);
      g_S0h[ix] = hi;
      g_S0l[ix] = __float2bfloat16(v - __bfloat162float(hi));
    }
  }
}

// out = h @ Wf^T + bf  (h = S0 hi+lo)
__global__ void __launch_bounds__(256, 1)
k_head(const float* __restrict__ Wf, const float* __restrict__ bf,
       float* __restrict__ out) {
  extern __shared__ float sm[];
  const int tid = threadIdx.x, b0 = blockIdx.x * 32;
  for (int idx = tid; idx < 32 * HID; idx += 256) {
    int m = idx >> 9, k = idx & 511;
    size_t ix = (size_t)(b0 + m) * HID + k;
    sm[k * 32 + m] = __bfloat162float(g_S0h[ix]) + __bfloat162float(g_S0l[ix]);
  }
  __syncthreads();
  const int row0 = (tid & 7) * 4, oc0 = (tid >> 3) * 4;
  float acc[4][4];
#pragma unroll
  for (int i = 0; i < 4; i++)
#pragma unroll
    for (int j = 0; j < 4; j++) acc[i][j] = 0.f;
#pragma unroll 1
  for (int k = 0; k < HID; k += 4) {
    float4 a[4];
#pragma unroll
    for (int kk = 0; kk < 4; kk++)
      a[kk] = *reinterpret_cast<const float4*>(sm + (k + kk) * 32 + row0);
#pragma unroll
    for (int j = 0; j < 4; j++) {
      float4 bb = *reinterpret_cast<const float4*>(Wf + (size_t)(oc0 + j) * HID + k);
      float bv[4] = {bb.x, bb.y, bb.z, bb.w};
#pragma unroll
      for (int kk = 0; kk < 4; kk++) {
        acc[0][j] = fmaf(a[kk].x, bv[kk], acc[0][j]);
        acc[1][j] = fmaf(a[kk].y, bv[kk], acc[1][j]);
        acc[2][j] = fmaf(a[kk].z, bv[kk], acc[2][j]);
        acc[3][j] = fmaf(a[kk].w, bv[kk], acc[3][j]);
      }
    }
  }
#pragma unroll
  for (int i = 0; i < 4; i++) {
    float4 o = make_float4(acc[i][0] + bf[oc0 + 0], acc[i][1] + bf[oc0 + 1],
                           acc[i][2] + bf[oc0 + 2], acc[i][3] + bf[oc0 + 3]);
    *reinterpret_cast<float4*>(out + (size_t)(b0 + row0 + i) * OUT_DIM + oc0) = o;
  }
}

// ---------------- HMMA GEMM kernel (stages + drive) ----------------
// MODE 0..3: RK4 stage. MODE 4: drive = u @ U^T + b.
// 256 threads, 8 warps (4M x 2N), warp tile 64x64, CTA tile 256 rows x 128 cols,
// 4 n-chunks of 128, K chunk = 64 (24 chunks for K'=1536), 3-stage cp.async.
#define APITCH   144
#define A_BYTES  36864           /* 256*144 */
#define B_BYTES  18432           /* 128*144 */
#define SSTRIDE  55296           /* A + B per stage */
#define NSTG     3
#define ST_SMEM  (NSTG * SSTRIDE)
#define MROWS    256

__device__ __forceinline__ void ld_chunk(uint32_t stg_base, int b0, int n0, int kc,
                                         int tid, const __nv_bfloat16* shi,
                                         const __nv_bfloat16* slo,
                                         const __nv_bfloat16* Bmat) {
  const __nv_bfloat16* asrc = ((kc >> 3) == 1) ? slo : shi;
  const int k0 = (kc & 7) << 6;
  const int kg = kc << 6;
  const int tr = tid >> 3;               // 0..31
  const int tc = tid & 7;                // 0..7 (16B segs of 128B row)
  uint32_t ad = stg_base + tr * APITCH + tc * 16;
  const __nv_bfloat16* ap = asrc + (((size_t)(b0 + tr)) << 9) + k0 + tc * 8;
#pragma unroll
  for (int j = 0; j < 8; j++) {          // 256 A rows
    cp16(ad, ap);
    ad += 32 * APITCH; ap += 32 * 512;
  }
  uint32_t bd = stg_base + A_BYTES + tr * APITCH + tc * 16;
  const __nv_bfloat16* bp = Bmat + (size_t)(n0 + tr) * 1536 + kg + tc * 8;
#pragma unroll
  for (int j = 0; j < 4; j++) {          // 128 B rows
    cp16(bd, bp);
    bd += 32 * APITCH; bp += 32 * 1536;
  }
}

template <int MODE>
__global__ void __launch_bounds__(256, 1) k_gemm(const float* __restrict__ bvec) {
  extern __shared__ __align__(128) char smem[];
  const uint32_t sb = smem_u32(smem);
  const int tid = threadIdx.x;
  const int lane = tid & 31, wid = tid >> 5;
  const int warp_m = wid & 3;            // 4 warps x 64 rows
  const int warp_n = wid >> 2;           // 2 warps x 64 cols
  const int b0 = blockIdx.x * MROWS;
  const int lr = lane & 15, lc = lane >> 4;

  const __nv_bfloat16* shi = (MODE == 4) ? g_S0h : Sh_ptr(MODE);
  const __nv_bfloat16* slo = (MODE == 4) ? g_S0l : Sl_ptr(MODE);
  const __nv_bfloat16* Bmat = (MODE == 4) ? g_Ubig : g_Wbig;
  __nv_bfloat16* dsth = (MODE == 4) ? g_S0h : Sh_ptr((MODE + 1) & 3);
  __nv_bfloat16* dstl = (MODE == 4) ? g_S0l : Sl_ptr((MODE + 1) & 3);

  const uint32_t a_off = (warp_m * 64 + lr) * APITCH + lc * 16;
  const uint32_t b_off = A_BYTES + (warp_n * 64 + lr) * APITCH + lc * 16;
  const uint32_t s_last = sb + 2 * SSTRIDE;

#pragma unroll 1
  for (int nc = 0; nc < 4; ++nc) {
    const int n0 = nc * 128;
    float acc[4][8][4];
#pragma unroll
    for (int i = 0; i < 4; i++)
#pragma unroll
      for (int j = 0; j < 8; j++)
#pragma unroll
        for (int q = 0; q < 4; q++) acc[i][j][q] = 0.f;

    ld_chunk(sb, b0, n0, 0, tid, shi, slo, Bmat); CP_COMMIT();
    ld_chunk(sb + SSTRIDE, b0, n0, 1, tid, shi, slo, Bmat); CP_COMMIT();

    uint32_t rd = sb, wr = sb + 2 * SSTRIDE;
#pragma unroll 1
    for (int kc = 0; kc < 24; ++kc) {
      CP_WAIT1();
      __syncthreads();
      const uint32_t ab = rd + a_off;
      const uint32_t bb = rd + b_off;
#pragma unroll
      for (int kk = 0; kk < 4; kk++) {
        uint32_t a[4][4], bfr[4][4];
#pragma unroll
        for (int q = 0; q < 4; q++)
          LDSM4(a[q][0], a[q][1], a[q][2], a[q][3],
                ab + q * 16 * APITCH + kk * 32);
#pragma unroll
        for (int q = 0; q < 4; q++)
          LDSM4(bfr[q][0], bfr[q][1], bfr[q][2], bfr[q][3],
                bb + q * 16 * APITCH + kk * 32);
#pragma unroll
        for (int fm = 0; fm < 4; fm++)
#pragma unroll
          for (int fn = 0; fn < 4; fn++) {
            MMA16816(acc[fm][2 * fn],     a[fm], bfr[fn][0], bfr[fn][2]);
            MMA16816(acc[fm][2 * fn + 1], a[fm], bfr[fn][1], bfr[fn][3]);
          }
      }
      if (kc < 22) ld_chunk(wr, b0, n0, kc + 2, tid, shi, slo, Bmat);
      CP_COMMIT();
      rd = (rd == s_last) ? sb : rd + SSTRIDE;
      wr = (wr == s_last) ? sb : wr + SSTRIDE;
    }

    // ---- fused epilogue on register fragments ----
    const int rq = lane >> 2, cq = (lane & 3) * 2;
#pragma unroll 1
    for (int fn = 0; fn < 8; fn++) {
      const int nn = n0 + warp_n * 64 + fn * 8 + cq;
#pragma unroll
      for (int fm = 0; fm < 4; fm++) {
#pragma unroll
        for (int half = 0; half < 2; half++) {
          const int r = b0 + warp_m * 64 + fm * 16 + rq + half * 8;
          const size_t ix = ((size_t)r << 9) + nn;
          const float c0 = acc[fm][fn][half * 2];
          const float c1 = acc[fm][fn][half * 2 + 1];
          if (MODE == 4) {
            float2 bv = *reinterpret_cast<const float2*>(bvec + nn);
            float2 o = make_float2(c0 + bv.x, c1 + bv.y);
            *reinterpret_cast<float2*>(g_drive + ix) = o;
          } else {
            const float2 it2 = *reinterpret_cast<const float2*>(g_itau + nn);
            float2 dr = *reinterpret_cast<const float2*>(g_drive + ix);
            __nv_bfloat162 sh2 = *reinterpret_cast<const __nv_bfloat162*>(shi + ix);
            __nv_bfloat162 sl2 = *reinterpret_cast<const __nv_bfloat162*>(slo + ix);
            float s0 = __bfloat162float(sh2.x) + __bfloat162float(sl2.x);
            float s1 = __bfloat162float(sh2.y) + __bfloat162float(sl2.y);
            float t0 = tanh_fast(c0 + dr.x);
            float t1 = tanh_fast(c1 + dr.y);
            float k0 = (t0 - s0) * it2.x;
            float k1 = (t1 - s1) * it2.y;
            float v0, v1;
            if (MODE == 0) {
              v0 = s0 + HDT * k0; v1 = s1 + HDT * k1;     // s2 = h + dt/2 k1
            } else {
              __nv_bfloat162 hh2 = *reinterpret_cast<const __nv_bfloat162*>(g_S0h + ix);
              __nv_bfloat162 hl2 = *reinterpret_cast<const __nv_bfloat162*>(g_S0l + ix);
              float h0 = __bfloat162float(hh2.x) + __bfloat162float(hl2.x);
              float h1 = __bfloat162float(hh2.y) + __bfloat162float(hl2.y);
              if (MODE == 1)      { v0 = h0 + HDT * k0; v1 = h1 + HDT * k1; }  // s3
              else if (MODE == 2) { v0 = h0 + DT * k0;  v1 = h1 + DT * k1;  }  // s4
              else {
                __nv_bfloat162 ah2 = *reinterpret_cast<const __nv_bfloat162*>(g_S1h + ix);
                __nv_bfloat162 al2 = *reinterpret_cast<const __nv_bfloat162*>(g_S1l + ix);
                __nv_bfloat162 bh2 = *reinterpret_cast<const __nv_bfloat162*>(g_S2h + ix);
                __nv_bfloat162 bl2 = *reinterpret_cast<const __nv_bfloat162*>(g_S2l + ix);
                float s20 = __bfloat162float(ah2.x) + __bfloat162float(al2.x);
                float s21 = __bfloat162float(ah2.y) + __bfloat162float(al2.y);
                float s30 = __bfloat162float(bh2.x) + __bfloat162float(bl2.x);
                float s31 = __bfloat162float(bh2.y) + __bfloat162float(bl2.y);
                v0 = h0 + (1.0f / 3.0f) * (s20 - h0) + (2.0f / 3.0f) * (s30 - h0)
                        + (1.0f / 3.0f) * (s0 - h0) + DT6 * k0;  // h_{n+1}
                v1 = h1 + (1.0f / 3.0f) * (s21 - h1) + (2.0f / 3.0f) * (s31 - h1)
                        + (1.0f / 3.0f) * (s1 - h1) + DT6 * k1;
              }
            }
            __nv_bfloat16 hi0 = __float2bfloat16(v0);
            __nv_bfloat16 hi1 = __float2bfloat16(v1);
            __nv_bfloat162 oh; oh.x = hi0; oh.y = hi1;
            __nv_bfloat162 ol;
            ol.x = __float2bfloat16(v0 - __bfloat162float(hi0));
            ol.y = __float2bfloat16(v1 - __bfloat162float(hi1));
            *reinterpret_cast<__nv_bfloat162*>(dsth + ix) = oh;
            *reinterpret_cast<__nv_bfloat162*>(dstl + ix) = ol;
          }
        }
      }
    }
    __syncthreads();   // stage buffers reused next nc
  }
}

// ---------------- launcher ----------------
extern "C" void kernel_launch(void* const* d_in, const int* in_sizes, int n_in,
                              void* d_out, int out_size) {
  (void)in_sizes; (void)n_in; (void)out_size;
  const float* x    = (const float*)d_in[0];
  const float* Wx   = (const float*)d_in[1];
  const float* bx   = (const float*)d_in[2];
  const float* W    = (const float*)d_in[3];
  const float* U    = (const float*)d_in[4];
  const float* bvec = (const float*)d_in[5];
  const float* tau  = (const float*)d_in[6];
  const float* Wf   = (const float*)d_in[7];
  const float* bf   = (const float*)d_in[8];
  float* out = (float*)d_out;

  cudaFuncSetAttribute(k_gemm<0>, cudaFuncAttributeMaxDynamicSharedMemorySize, ST_SMEM);
  cudaFuncSetAttribute(k_gemm<1>, cudaFuncAttributeMaxDynamicSharedMemorySize, ST_SMEM);
  cudaFuncSetAttribute(k_gemm<2>, cudaFuncAttributeMaxDynamicSharedMemorySize, ST_SMEM);
  cudaFuncSetAttribute(k_gemm<3>, cudaFuncAttributeMaxDynamicSharedMemorySize, ST_SMEM);
  cudaFuncSetAttribute(k_gemm<4>, cudaFuncAttributeMaxDynamicSharedMemorySize, ST_SMEM);
  cudaFuncSetAttribute(k_head,  cudaFuncAttributeMaxDynamicSharedMemorySize, 65536);
  cudaFuncSetAttribute(k_in,    cudaFuncAttributeMaxDynamicSharedMemorySize, 32768);

  k_prep<<<(2 * 512 * 1536) / 256, 256>>>(W, U, tau);
  k_in<<<BATCH / 32, 256, 32768>>>(x, Wx, bx);
  k_gemm<4><<<BATCH / MROWS, 256, ST_SMEM>>>(bvec);      // drive
  for (int step = 0; step < NSTEPS; ++step) {
    k_gemm<0><<<BATCH / MROWS, 256, ST_SMEM>>>(nullptr);
    k_gemm<1><<<BATCH / MROWS, 256, ST_SMEM>>>(nullptr);
    k_gemm<2><<<BATCH / MROWS, 256, ST_SMEM>>>(nullptr);
    k_gemm<3><<<BATCH / MROWS, 256, ST_SMEM>>>(nullptr);
  }
  k_head<<<BATCH / 32, 256, 65536>>>(Wf, bf, out);
}

// round 8
// speedup vs baseline: 2.2692x; 2.2692x over previous
#include <cuda_runtime.h>
#include <cuda_bf16.h>
#include <cstdint>

#define BATCH    32768
#define IN_DIM   256
#define HID      512
#define OUT_DIM  128
#define NSTEPS   40
#define DT       0.025f
#define HDT      0.0125f
#define DT6      (0.025f / 6.0f)

// ---------------- static device scratch ----------------
__device__ __align__(128) __nv_bfloat16 g_S0h[(size_t)BATCH * HID];
__device__ __align__(128) __nv_bfloat16 g_S0l[(size_t)BATCH * HID];
__device__ __align__(128) __nv_bfloat16 g_S1h[(size_t)BATCH * HID];
__device__ __align__(128) __nv_bfloat16 g_S1l[(size_t)BATCH * HID];
__device__ __align__(128) __nv_bfloat16 g_S2h[(size_t)BATCH * HID];
__device__ __align__(128) __nv_bfloat16 g_S2l[(size_t)BATCH * HID];
__device__ __align__(128) __nv_bfloat16 g_S3h[(size_t)BATCH * HID];
__device__ __align__(128) __nv_bfloat16 g_S3l[(size_t)BATCH * HID];
__device__ __align__(128) __nv_bfloat16 g_Wbig[(size_t)HID * 1536];  // [n][k']: Whi|Whi|Wlo
__device__ __align__(128) __nv_bfloat16 g_Ubig[(size_t)HID * 1536];  // [n][k']: Uhi|Uhi|Ulo
__device__ __align__(128) float g_drive[(size_t)BATCH * HID];
__device__ __align__(128) float g_itau[HID];

__device__ __forceinline__ __nv_bfloat16* Sh_ptr(int i) {
  switch (i) { case 0: return g_S0h; case 1: return g_S1h; case 2: return g_S2h; default: return g_S3h; }
}
__device__ __forceinline__ __nv_bfloat16* Sl_ptr(int i) {
  switch (i) { case 0: return g_S0l; case 1: return g_S1l; case 2: return g_S2l; default: return g_S3l; }
}

// ---------------- helpers ----------------
__device__ __forceinline__ uint32_t smem_u32(const void* p) {
  uint32_t a;
  asm("{ .reg .u64 t; cvta.to.shared.u64 t, %1; cvt.u32.u64 %0, t; }" : "=r"(a) : "l"(p));
  return a;
}
__device__ __forceinline__ void cp16(uint32_t dst, const void* src) {
  asm volatile("cp.async.cg.shared.global [%0], [%1], 16;" :: "r"(dst), "l"(src) : "memory");
}
#define CP_COMMIT() asm volatile("cp.async.commit_group;" ::: "memory")
#define CP_WAIT1()  asm volatile("cp.async.wait_group 1;" ::: "memory")

#define LDSM4(r0, r1, r2, r3, a) \
  asm volatile("ldmatrix.sync.aligned.m8n8.x4.shared.b16 {%0,%1,%2,%3}, [%4];" \
               : "=r"(r0), "=r"(r1), "=r"(r2), "=r"(r3) : "r"(a))

#define MMA16816(d, a, b0, b1) \
  asm volatile("mma.sync.aligned.m16n8k16.row.col.f32.bf16.bf16.f32 " \
               "{%0,%1,%2,%3},{%4,%5,%6,%7},{%8,%9},{%0,%1,%2,%3};" \
               : "+f"((d)[0]), "+f"((d)[1]), "+f"((d)[2]), "+f"((d)[3]) \
               : "r"((a)[0]), "r"((a)[1]), "r"((a)[2]), "r"((a)[3]), "r"(b0), "r"(b1))

__device__ __forceinline__ float tanh_fast(float x) {
  float e = __expf(2.0f * x);
  return 1.0f - __fdividef(2.0f, e + 1.0f);
}

// ---------------- prep: W/U -> [hi | hi | lo] bf16, itau ----------------
__global__ void k_prep(const float* __restrict__ W, const float* __restrict__ U,
                       const float* __restrict__ tau) {
  int idx = blockIdx.x * 256 + threadIdx.x;           // 2*512*1536 total
  const int HALF = 512 * 1536;
  int h = (idx >= HALF) ? 1 : 0;
  int j = idx - h * HALF;
  int n = j / 1536, k = j % 1536;
  int kk = k & 511, region = k >> 9;
  const float* src = h ? U : W;
  __nv_bfloat16* dst = h ? g_Ubig : g_Wbig;
  float w = src[n * 512 + kk];
  __nv_bfloat16 hi = __float2bfloat16(w);
  dst[j] = (region < 2) ? hi : __float2bfloat16(w - __bfloat162float(hi));
  if (idx < HID) g_itau[idx] = 1.0f / tau[idx];
}

// ---------------- fp32 microtile GEMM (k_in / k_head) ----------------
template <int K>
__device__ __forceinline__ void gemm_tile(const float* __restrict__ As,
                                          const float* __restrict__ Bg,
                                          int row0, int col0, float acc[4][16]) {
#pragma unroll
  for (int i = 0; i < 4; i++)
#pragma unroll
    for (int j = 0; j < 16; j++) acc[i][j] = 0.f;
#pragma unroll 1
  for (int k = 0; k < K; k += 4) {
    float4 a[4];
#pragma unroll
    for (int kk = 0; kk < 4; kk++)
      a[kk] = *reinterpret_cast<const float4*>(As + (k + kk) * 32 + row0);
    float4 bb[16];
#pragma unroll
    for (int j = 0; j < 16; j++)
      bb[j] = *reinterpret_cast<const float4*>(Bg + (size_t)(col0 + j) * K + k);
#pragma unroll
    for (int j = 0; j < 16; j++) {
      float bv[4] = {bb[j].x, bb[j].y, bb[j].z, bb[j].w};
#pragma unroll
      for (int kk = 0; kk < 4; kk++) {
        acc[0][j] = fmaf(a[kk].x, bv[kk], acc[0][j]);
        acc[1][j] = fmaf(a[kk].y, bv[kk], acc[1][j]);
        acc[2][j] = fmaf(a[kk].z, bv[kk], acc[2][j]);
        acc[3][j] = fmaf(a[kk].w, bv[kk], acc[3][j]);
      }
    }
  }
}

// u = x @ Wx^T + bx ; writes S0 (h0 = u) as bf16 hi/lo
__global__ void __launch_bounds__(256, 1)
k_in(const float* __restrict__ x, const float* __restrict__ Wx,
     const float* __restrict__ bx) {
  extern __shared__ float sm[];
  const int tid = threadIdx.x, b0 = blockIdx.x * 32;
  for (int idx = tid; idx < 32 * IN_DIM; idx += 256) {
    int m = idx >> 8, k = idx & 255;
    sm[k * 32 + m] = x[(size_t)(b0 + m) * IN_DIM + k];
  }
  __syncthreads();
  const int row0 = (tid & 7) * 4, col0 = (tid >> 3) * 16;
  float acc[4][16];
  gemm_tile<IN_DIM>(sm, Wx, row0, col0, acc);
#pragma unroll
  for (int j = 0; j < 16; j++) {
    float bxi = bx[col0 + j];
#pragma unroll
    for (int i = 0; i < 4; i++) {
      float v = acc[i][j] + bxi;
      size_t ix = (size_t)(b0 + row0 + i) * HID + col0 + j;
      __nv_bfloat16 hi = __float2bfloat16(v);
      g_S0h[ix] = hi;
      g_S0l[ix] = __float2bfloat16(v - __bfloat162float(hi));
    }
  }
}

// out = h @ Wf^T + bf  (h = S0 hi+lo)
__global__ void __launch_bounds__(256, 1)
k_head(const float* __restrict__ Wf, const float* __restrict__ bf,
       float* __restrict__ out) {
  extern __shared__ float sm[];
  const int tid = threadIdx.x, b0 = blockIdx.x * 32;
  for (int idx = tid; idx < 32 * HID; idx += 256) {
    int m = idx >> 9, k = idx & 511;
    size_t ix = (size_t)(b0 + m) * HID + k;
    sm[k * 32 + m] = __bfloat162float(g_S0h[ix]) + __bfloat162float(g_S0l[ix]);
  }
  __syncthreads();
  const int row0 = (tid & 7) * 4, oc0 = (tid >> 3) * 4;
  float acc[4][4];
#pragma unroll
  for (int i = 0; i < 4; i++)
#pragma unroll
    for (int j = 0; j < 4; j++) acc[i][j] = 0.f;
#pragma unroll 1
  for (int k = 0; k < HID; k += 4) {
    float4 a[4];
#pragma unroll
    for (int kk = 0; kk < 4; kk++)
      a[kk] = *reinterpret_cast<const float4*>(sm + (k + kk) * 32 + row0);
#pragma unroll
    for (int j = 0; j < 4; j++) {
      float4 bb = *reinterpret_cast<const float4*>(Wf + (size_t)(oc0 + j) * HID + k);
      float bv[4] = {bb.x, bb.y, bb.z, bb.w};
#pragma unroll
      for (int kk = 0; kk < 4; kk++) {
        acc[0][j] = fmaf(a[kk].x, bv[kk], acc[0][j]);
        acc[1][j] = fmaf(a[kk].y, bv[kk], acc[1][j]);
        acc[2][j] = fmaf(a[kk].z, bv[kk], acc[2][j]);
        acc[3][j] = fmaf(a[kk].w, bv[kk], acc[3][j]);
      }
    }
  }
#pragma unroll
  for (int i = 0; i < 4; i++) {
    float4 o = make_float4(acc[i][0] + bf[oc0 + 0], acc[i][1] + bf[oc0 + 1],
                           acc[i][2] + bf[oc0 + 2], acc[i][3] + bf[oc0 + 3]);
    *reinterpret_cast<float4*>(out + (size_t)(b0 + row0 + i) * OUT_DIM + oc0) = o;
  }
}

// ---------------- HMMA GEMM kernel (stages + drive) ----------------
// MODE 0..3: RK4 stage. MODE 4: drive = u @ U^T + b.
// 512 threads, 16 warps (4M x 4N), warp tile 32x64 (64 accs/thread),
// CTA tile 128 rows x 256 cols -> 2 n-chunks. K chunk = 64 (24 chunks),
// 3-stage cp.async pipeline.
#define APITCH   144
#define A_BYTES  18432           /* 128*144 */
#define B_BYTES  36864           /* 256*144 */
#define SSTRIDE  55296           /* A + B per stage */
#define NSTG     3
#define ST_SMEM  (NSTG * SSTRIDE)

__device__ __forceinline__ void ld_chunk(uint32_t stg_base, int b0, int n0, int kc,
                                         int tid, const __nv_bfloat16* shi,
                                         const __nv_bfloat16* slo,
                                         const __nv_bfloat16* Bmat) {
  const __nv_bfloat16* asrc = ((kc >> 3) == 1) ? slo : shi;
  const int k0 = (kc & 7) << 6;
  const int kg = kc << 6;
  const int r = tid >> 3;                // 0..63
  const int c = tid & 7;                 // 16B seg
  // A: 128 rows
#pragma unroll
  for (int j = 0; j < 2; j++) {
    int rr = r + j * 64;
    cp16(stg_base + rr * APITCH + c * 16,
         asrc + (((size_t)(b0 + rr)) << 9) + k0 + c * 8);
  }
  // B: 256 rows
#pragma unroll
  for (int j = 0; j < 4; j++) {
    int rr = r + j * 64;
    cp16(stg_base + A_BYTES + rr * APITCH + c * 16,
         Bmat + (size_t)(n0 + rr) * 1536 + kg + c * 8);
  }
}

template <int MODE>
__global__ void __launch_bounds__(512, 1) k_gemm(const float* __restrict__ bvec) {
  extern __shared__ __align__(128) char smem[];
  const uint32_t sb = smem_u32(smem);
  const int tid = threadIdx.x;
  const int lane = tid & 31, wid = tid >> 5;
  const int warp_m = wid & 3;            // 4 warps x 32 rows
  const int warp_n = wid >> 2;           // 4 warps x 64 cols
  const int b0 = blockIdx.x * 128;
  const int lr = lane & 15, lc = lane >> 4;

  const __nv_bfloat16* shi = (MODE == 4) ? g_S0h : Sh_ptr(MODE);
  const __nv_bfloat16* slo = (MODE == 4) ? g_S0l : Sl_ptr(MODE);
  const __nv_bfloat16* Bmat = (MODE == 4) ? g_Ubig : g_Wbig;
  __nv_bfloat16* dsth = (MODE == 4) ? g_S0h : Sh_ptr((MODE + 1) & 3);
  __nv_bfloat16* dstl = (MODE == 4) ? g_S0l : Sl_ptr((MODE + 1) & 3);

  const uint32_t a_off = (warp_m * 32 + lr) * APITCH + lc * 16;
  const uint32_t b_off = A_BYTES + (warp_n * 64 + lr) * APITCH + lc * 16;
  const uint32_t s_last = sb + 2 * SSTRIDE;

#pragma unroll 1
  for (int nc = 0; nc < 2; ++nc) {
    const int n0 = nc * 256;
    float acc[2][8][4];                  // 64 accs: fm(2x16 rows) x fn(8x8 cols)
#pragma unroll
    for (int i = 0; i < 2; i++)
#pragma unroll
      for (int j = 0; j < 8; j++)
#pragma unroll
        for (int q = 0; q < 4; q++) acc[i][j][q] = 0.f;

    ld_chunk(sb, b0, n0, 0, tid, shi, slo, Bmat); CP_COMMIT();
    ld_chunk(sb + SSTRIDE, b0, n0, 1, tid, shi, slo, Bmat); CP_COMMIT();

    uint32_t rd = sb, wr = sb + 2 * SSTRIDE;
#pragma unroll 1
    for (int kc = 0; kc < 24; ++kc) {
      CP_WAIT1();
      __syncthreads();
      const uint32_t ab = rd + a_off;
      const uint32_t bb = rd + b_off;
#pragma unroll
      for (int kk = 0; kk < 4; kk++) {
        uint32_t a[2][4], bfr[4][4];
        LDSM4(a[0][0], a[0][1], a[0][2], a[0][3], ab + kk * 32);
        LDSM4(a[1][0], a[1][1], a[1][2], a[1][3], ab + 16 * APITCH + kk * 32);
#pragma unroll
        for (int q = 0; q < 4; q++)
          LDSM4(bfr[q][0], bfr[q][1], bfr[q][2], bfr[q][3],
                bb + q * 16 * APITCH + kk * 32);
#pragma unroll
        for (int fm = 0; fm < 2; fm++)
#pragma unroll
          for (int fn = 0; fn < 4; fn++) {
            MMA16816(acc[fm][2 * fn],     a[fm], bfr[fn][0], bfr[fn][2]);
            MMA16816(acc[fm][2 * fn + 1], a[fm], bfr[fn][1], bfr[fn][3]);
          }
      }
      if (kc < 22) ld_chunk(wr, b0, n0, kc + 2, tid, shi, slo, Bmat);
      CP_COMMIT();
      rd = (rd == s_last) ? sb : rd + SSTRIDE;
      wr = (wr == s_last) ? sb : wr + SSTRIDE;
    }

    // ---- fused epilogue on register fragments ----
    const int rq = lane >> 2, cq = (lane & 3) * 2;
#pragma unroll 1
    for (int fn = 0; fn < 8; fn++) {
      const int nn = n0 + warp_n * 64 + fn * 8 + cq;
#pragma unroll
      for (int fm = 0; fm < 2; fm++) {
#pragma unroll
        for (int half = 0; half < 2; half++) {
          const int r = b0 + warp_m * 32 + fm * 16 + rq + half * 8;
          const size_t ix = ((size_t)r << 9) + nn;
          const float c0 = acc[fm][fn][half * 2];
          const float c1 = acc[fm][fn][half * 2 + 1];
          if (MODE == 4) {
            float2 bv = *reinterpret_cast<const float2*>(bvec + nn);
            float2 o = make_float2(c0 + bv.x, c1 + bv.y);
            *reinterpret_cast<float2*>(g_drive + ix) = o;
          } else {
            const float2 it2 = *reinterpret_cast<const float2*>(g_itau + nn);
            float2 dr = *reinterpret_cast<const float2*>(g_drive + ix);
            __nv_bfloat162 sh2 = *reinterpret_cast<const __nv_bfloat162*>(shi + ix);
            __nv_bfloat162 sl2 = *reinterpret_cast<const __nv_bfloat162*>(slo + ix);
            float s0 = __bfloat162float(sh2.x) + __bfloat162float(sl2.x);
            float s1 = __bfloat162float(sh2.y) + __bfloat162float(sl2.y);
            float t0 = tanh_fast(c0 + dr.x);
            float t1 = tanh_fast(c1 + dr.y);
            float k0 = (t0 - s0) * it2.x;
            float k1 = (t1 - s1) * it2.y;
            float v0, v1;
            if (MODE == 0) {
              v0 = s0 + HDT * k0; v1 = s1 + HDT * k1;     // s2 = h + dt/2 k1
            } else {
              __nv_bfloat162 hh2 = *reinterpret_cast<const __nv_bfloat162*>(g_S0h + ix);
              __nv_bfloat162 hl2 = *reinterpret_cast<const __nv_bfloat162*>(g_S0l + ix);
              float h0 = __bfloat162float(hh2.x) + __bfloat162float(hl2.x);
              float h1 = __bfloat162float(hh2.y) + __bfloat162float(hl2.y);
              if (MODE == 1)      { v0 = h0 + HDT * k0; v1 = h1 + HDT * k1; }  // s3
              else if (MODE == 2) { v0 = h0 + DT * k0;  v1 = h1 + DT * k1;  }  // s4
              else {
                __nv_bfloat162 ah2 = *reinterpret_cast<const __nv_bfloat162*>(g_S1h + ix);
                __nv_bfloat162 al2 = *reinterpret_cast<const __nv_bfloat162*>(g_S1l + ix);
                __nv_bfloat162 bh2 = *reinterpret_cast<const __nv_bfloat162*>(g_S2h + ix);
                __nv_bfloat162 bl2 = *reinterpret_cast<const __nv_bfloat162*>(g_S2l + ix);
                float s20 = __bfloat162float(ah2.x) + __bfloat162float(al2.x);
                float s21 = __bfloat162float(ah2.y) + __bfloat162float(al2.y);
                float s30 = __bfloat162float(bh2.x) + __bfloat162float(bl2.x);
                float s31 = __bfloat162float(bh2.y) + __bfloat162float(bl2.y);
                v0 = h0 + (1.0f / 3.0f) * (s20 - h0) + (2.0f / 3.0f) * (s30 - h0)
                        + (1.0f / 3.0f) * (s0 - h0) + DT6 * k0;  // h_{n+1}
                v1 = h1 + (1.0f / 3.0f) * (s21 - h1) + (2.0f / 3.0f) * (s31 - h1)
                        + (1.0f / 3.0f) * (s1 - h1) + DT6 * k1;
              }
            }
            __nv_bfloat16 hi0 = __float2bfloat16(v0);
            __nv_bfloat16 hi1 = __float2bfloat16(v1);
            __nv_bfloat162 oh; oh.x = hi0; oh.y = hi1;
            __nv_bfloat162 ol;
            ol.x = __float2bfloat16(v0 - __bfloat162float(hi0));
            ol.y = __float2bfloat16(v1 - __bfloat162float(hi1));
            *reinterpret_cast<__nv_bfloat162*>(dsth + ix) = oh;
            *reinterpret_cast<__nv_bfloat162*>(dstl + ix) = ol;
          }
        }
      }
    }
    __syncthreads();   // stage buffers reused next nc
  }
}

// ---------------- launcher ----------------
extern "C" void kernel_launch(void* const* d_in, const int* in_sizes, int n_in,
                              void* d_out, int out_size) {
  (void)in_sizes; (void)n_in; (void)out_size;
  const float* x    = (const float*)d_in[0];
  const float* Wx   = (const float*)d_in[1];
  const float* bx   = (const float*)d_in[2];
  const float* W    = (const float*)d_in[3];
  const float* U    = (const float*)d_in[4];
  const float* bvec = (const float*)d_in[5];
  const float* tau  = (const float*)d_in[6];
  const float* Wf   = (const float*)d_in[7];
  const float* bf   = (const float*)d_in[8];
  float* out = (float*)d_out;

  cudaFuncSetAttribute(k_gemm<0>, cudaFuncAttributeMaxDynamicSharedMemorySize, ST_SMEM);
  cudaFuncSetAttribute(k_gemm<1>, cudaFuncAttributeMaxDynamicSharedMemorySize, ST_SMEM);
  cudaFuncSetAttribute(k_gemm<2>, cudaFuncAttributeMaxDynamicSharedMemorySize, ST_SMEM);
  cudaFuncSetAttribute(k_gemm<3>, cudaFuncAttributeMaxDynamicSharedMemorySize, ST_SMEM);
  cudaFuncSetAttribute(k_gemm<4>, cudaFuncAttributeMaxDynamicSharedMemorySize, ST_SMEM);
  cudaFuncSetAttribute(k_head,  cudaFuncAttributeMaxDynamicSharedMemorySize, 65536);
  cudaFuncSetAttribute(k_in,    cudaFuncAttributeMaxDynamicSharedMemorySize, 32768);

  k_prep<<<(2 * 512 * 1536) / 256, 256>>>(W, U, tau);
  k_in<<<BATCH / 32, 256, 32768>>>(x, Wx, bx);
  k_gemm<4><<<BATCH / 128, 512, ST_SMEM>>>(bvec);        // drive
  for (int step = 0; step < NSTEPS; ++step) {
    k_gemm<0><<<BATCH / 128, 512, ST_SMEM>>>(nullptr);
    k_gemm<1><<<BATCH / 128, 512, ST_SMEM>>>(nullptr);
    k_gemm<2><<<BATCH / 128, 512, ST_SMEM>>>(nullptr);
    k_gemm<3><<<BATCH / 128, 512, ST_SMEM>>>(nullptr);
  }
  k_head<<<BATCH / 32, 256, 65536>>>(Wf, bf, out);
}

// round 9
// speedup vs baseline: 4.4034x; 1.9405x over previous
#include <cuda_runtime.h>
#include <cuda_bf16.h>
#include <cstdint>

#define BATCH    32768
#define IN_DIM   256
#define HID      512
#define OUT_DIM  128
#define NSTEPS   40
#define DT       0.025f
#define HDT      0.0125f
#define DT6      (0.025f / 6.0f)

// ---------------- static device scratch ----------------
__device__ __align__(128) __nv_bfloat16 g_S0h[(size_t)BATCH * HID];
__device__ __align__(128) __nv_bfloat16 g_S0l[(size_t)BATCH * HID];
__device__ __align__(128) __nv_bfloat16 g_S1h[(size_t)BATCH * HID];
__device__ __align__(128) __nv_bfloat16 g_S1l[(size_t)BATCH * HID];
__device__ __align__(128) __nv_bfloat16 g_S2h[(size_t)BATCH * HID];
__device__ __align__(128) __nv_bfloat16 g_S2l[(size_t)BATCH * HID];
__device__ __align__(128) __nv_bfloat16 g_S3h[(size_t)BATCH * HID];
__device__ __align__(128) __nv_bfloat16 g_S3l[(size_t)BATCH * HID];
__device__ __align__(128) __nv_bfloat16 g_Wbig[(size_t)HID * 1536];  // [n][k']: Whi|Whi|Wlo
__device__ __align__(128) __nv_bfloat16 g_Ubig[(size_t)HID * 1536];  // [n][k']: Uhi|Uhi|Ulo
__device__ __align__(128) float g_drive[(size_t)BATCH * HID];
__device__ __align__(128) float g_itau[HID];

__device__ __forceinline__ __nv_bfloat16* Sh_ptr(int i) {
  switch (i) { case 0: return g_S0h; case 1: return g_S1h; case 2: return g_S2h; default: return g_S3h; }
}
__device__ __forceinline__ __nv_bfloat16* Sl_ptr(int i) {
  switch (i) { case 0: return g_S0l; case 1: return g_S1l; case 2: return g_S2l; default: return g_S3l; }
}

// ---------------- helpers ----------------
__device__ __forceinline__ uint32_t smem_u32(const void* p) {
  uint32_t a;
  asm("{ .reg .u64 t; cvta.to.shared.u64 t, %1; cvt.u32.u64 %0, t; }" : "=r"(a) : "l"(p));
  return a;
}
__device__ __forceinline__ void cp16(uint32_t dst, const void* src) {
  asm volatile("cp.async.cg.shared.global [%0], [%1], 16;" :: "r"(dst), "l"(src) : "memory");
}
#define MBARRIER_INIT(a, c) \
  asm volatile("mbarrier.init.shared.b64 [%0], %1;" :: "r"(a), "r"((uint32_t)(c)) : "memory")
#define MBARRIER_ARRIVE(a) \
  asm volatile("mbarrier.arrive.shared.b64 _, [%0];" :: "r"(a) : "memory")
#define CPASYNC_MBAR_ARRIVE(a) \
  asm volatile("cp.async.mbarrier.arrive.noinc.shared::cta.b64 [%0];" :: "r"(a) : "memory")
#define MBAR_WAIT(a, ph) do {                                              \
  uint32_t _m = (a), _p = (uint32_t)(ph), _d;                              \
  asm volatile("{ .reg .pred p; mbarrier.try_wait.parity.acquire.cta.shared::cta.b64 p, [%1], %2; selp.b32 %0,1,0,p; }" \
               : "=r"(_d) : "r"(_m), "r"(_p) : "memory");                  \
  if (!_d) {                                                               \
    asm volatile("{ .reg .pred P1; WL%=: mbarrier.try_wait.parity.acquire.cta.shared::cta.b64 P1, [%0], %1, 0x989680; @P1 bra.uni WD%=; bra.uni WL%=; WD%=: }" \
                 :: "r"(_m), "r"(_p) : "memory");                          \
  }                                                                        \
} while (0)

#define LDSM4(r0, r1, r2, r3, a) \
  asm volatile("ldmatrix.sync.aligned.m8n8.x4.shared.b16 {%0,%1,%2,%3}, [%4];" \
               : "=r"(r0), "=r"(r1), "=r"(r2), "=r"(r3) : "r"(a))

#define MMA16816(d, a, b0, b1) \
  asm volatile("mma.sync.aligned.m16n8k16.row.col.f32.bf16.bf16.f32 " \
               "{%0,%1,%2,%3},{%4,%5,%6,%7},{%8,%9},{%0,%1,%2,%3};" \
               : "+f"((d)[0]), "+f"((d)[1]), "+f"((d)[2]), "+f"((d)[3]) \
               : "r"((a)[0]), "r"((a)[1]), "r"((a)[2]), "r"((a)[3]), "r"(b0), "r"(b1))

__device__ __forceinline__ float tanh_fast(float x) {
  float e = __expf(2.0f * x);
  return 1.0f - __fdividef(2.0f, e + 1.0f);
}

// ---------------- prep: W/U -> [hi | hi | lo] bf16, itau ----------------
__global__ void k_prep(const float* __restrict__ W, const float* __restrict__ U,
                       const float* __restrict__ tau) {
  int idx = blockIdx.x * 256 + threadIdx.x;           // 2*512*1536 total
  const int HALF = 512 * 1536;
  int h = (idx >= HALF) ? 1 : 0;
  int j = idx - h * HALF;
  int n = j / 1536, k = j % 1536;
  int kk = k & 511, region = k >> 9;
  const float* src = h ? U : W;
  __nv_bfloat16* dst = h ? g_Ubig : g_Wbig;
  float w = src[n * 512 + kk];
  __nv_bfloat16 hi = __float2bfloat16(w);
  dst[j] = (region < 2) ? hi : __float2bfloat16(w - __bfloat162float(hi));
  if (idx < HID) g_itau[idx] = 1.0f / tau[idx];
}

// ---------------- fp32 microtile GEMM (k_in / k_head) ----------------
template <int K>
__device__ __forceinline__ void gemm_tile(const float* __restrict__ As,
                                          const float* __restrict__ Bg,
                                          int row0, int col0, float acc[4][16]) {
#pragma unroll
  for (int i = 0; i < 4; i++)
#pragma unroll
    for (int j = 0; j < 16; j++) acc[i][j] = 0.f;
#pragma unroll 1
  for (int k = 0; k < K; k += 4) {
    float4 a[4];
#pragma unroll
    for (int kk = 0; kk < 4; kk++)
      a[kk] = *reinterpret_cast<const float4*>(As + (k + kk) * 32 + row0);
    float4 bb[16];
#pragma unroll
    for (int j = 0; j < 16; j++)
      bb[j] = *reinterpret_cast<const float4*>(Bg + (size_t)(col0 + j) * K + k);
#pragma unroll
    for (int j = 0; j < 16; j++) {
      float bv[4] = {bb[j].x, bb[j].y, bb[j].z, bb[j].w};
#pragma unroll
      for (int kk = 0; kk < 4; kk++) {
        acc[0][j] = fmaf(a[kk].x, bv[kk], acc[0][j]);
        acc[1][j] = fmaf(a[kk].y, bv[kk], acc[1][j]);
        acc[2][j] = fmaf(a[kk].z, bv[kk], acc[2][j]);
        acc[3][j] = fmaf(a[kk].w, bv[kk], acc[3][j]);
      }
    }
  }
}

// u = x @ Wx^T + bx ; writes S0 (h0 = u) as bf16 hi/lo
__global__ void __launch_bounds__(256, 1)
k_in(const float* __restrict__ x, const float* __restrict__ Wx,
     const float* __restrict__ bx) {
  extern __shared__ float sm[];
  const int tid = threadIdx.x, b0 = blockIdx.x * 32;
  for (int idx = tid; idx < 32 * IN_DIM; idx += 256) {
    int m = idx >> 8, k = idx & 255;
    sm[k * 32 + m] = x[(size_t)(b0 + m) * IN_DIM + k];
  }
  __syncthreads();
  const int row0 = (tid & 7) * 4, col0 = (tid >> 3) * 16;
  float acc[4][16];
  gemm_tile<IN_DIM>(sm, Wx, row0, col0, acc);
#pragma unroll
  for (int j = 0; j < 16; j++) {
    float bxi = bx[col0 + j];
#pragma unroll
    for (int i = 0; i < 4; i++) {
      float v = acc[i][j] + bxi;
      size_t ix = (size_t)(b0 + row0 + i) * HID + col0 + j;
      __nv_bfloat16 hi = __float2bfloat16(v);
      g_S0h[ix] = hi;
      g_S0l[ix] = __float2bfloat16(v - __bfloat162float(hi));
    }
  }
}

// out = h @ Wf^T + bf  (h = S0 hi+lo)
__global__ void __launch_bounds__(256, 1)
k_head(const float* __restrict__ Wf, const float* __restrict__ bf,
       float* __restrict__ out) {
  extern __shared__ float sm[];
  const int tid = threadIdx.x, b0 = blockIdx.x * 32;
  for (int idx = tid; idx < 32 * HID; idx += 256) {
    int m = idx >> 9, k = idx & 511;
    size_t ix = (size_t)(b0 + m) * HID + k;
    sm[k * 32 + m] = __bfloat162float(g_S0h[ix]) + __bfloat162float(g_S0l[ix]);
  }
  __syncthreads();
  const int row0 = (tid & 7) * 4, oc0 = (tid >> 3) * 4;
  float acc[4][4];
#pragma unroll
  for (int i = 0; i < 4; i++)
#pragma unroll
    for (int j = 0; j < 4; j++) acc[i][j] = 0.f;
#pragma unroll 1
  for (int k = 0; k < HID; k += 4) {
    float4 a[4];
#pragma unroll
    for (int kk = 0; kk < 4; kk++)
      a[kk] = *reinterpret_cast<const float4*>(sm + (k + kk) * 32 + row0);
#pragma unroll
    for (int j = 0; j < 4; j++) {
      float4 bb = *reinterpret_cast<const float4*>(Wf + (size_t)(oc0 + j) * HID + k);
      float bv[4] = {bb.x, bb.y, bb.z, bb.w};
#pragma unroll
      for (int kk = 0; kk < 4; kk++) {
        acc[0][j] = fmaf(a[kk].x, bv[kk], acc[0][j]);
        acc[1][j] = fmaf(a[kk].y, bv[kk], acc[1][j]);
        acc[2][j] = fmaf(a[kk].z, bv[kk], acc[2][j]);
        acc[3][j] = fmaf(a[kk].w, bv[kk], acc[3][j]);
      }
    }
  }
#pragma unroll
  for (int i = 0; i < 4; i++) {
    float4 o = make_float4(acc[i][0] + bf[oc0 + 0], acc[i][1] + bf[oc0 + 1],
                           acc[i][2] + bf[oc0 + 2], acc[i][3] + bf[oc0 + 3]);
    *reinterpret_cast<float4*>(out + (size_t)(b0 + row0 + i) * OUT_DIM + oc0) = o;
  }
}

// ---------------- warp-specialized HMMA GEMM kernel ----------------
// MODE 0..3: RK4 stage. MODE 4: drive = u @ U^T + b.
// 576 threads: 16 consumer warps (4M x 4N, 32x32 tiles, 128 rows x 128 cols/nc,
// 4 n-chunks) + 2 producer warps streaming a 4-stage cp.async ring.
// K chunk = 64 (24 chunks/nc, 96 chunks total). mbarrier full/empty per stage.
#define APITCH     144
#define A_BYTES    18432          /* 128*144 */
#define SSTRIDE    36864          /* A + B per stage */
#define NSTG       4
#define RING_BYTES (NSTG * SSTRIDE)
#define ST_SMEM    (RING_BYTES + 128)
#define N_CONS     512
#define N_PROD     64
#define NTHR       (N_CONS + N_PROD)

template <int MODE>
__global__ void __launch_bounds__(NTHR, 1) k_gemm(const float* __restrict__ bvec) {
  extern __shared__ __align__(128) char smem[];
  const uint32_t sb = smem_u32(smem);
  const uint32_t bar = sb + RING_BYTES;      // full[s]@bar+16s, empty[s]@bar+16s+8
  const int tid = threadIdx.x;
  const int b0 = blockIdx.x * 128;

  const __nv_bfloat16* shi = (MODE == 4) ? g_S0h : Sh_ptr(MODE);
  const __nv_bfloat16* slo = (MODE == 4) ? g_S0l : Sl_ptr(MODE);
  const __nv_bfloat16* Bmat = (MODE == 4) ? g_Ubig : g_Wbig;
  __nv_bfloat16* dsth = (MODE == 4) ? g_S0h : Sh_ptr((MODE + 1) & 3);
  __nv_bfloat16* dstl = (MODE == 4) ? g_S0l : Sl_ptr((MODE + 1) & 3);

  if (tid == 0) {
#pragma unroll
    for (int s = 0; s < NSTG; s++) {
      MBARRIER_INIT(bar + s * 16, N_PROD);   // full: one cp.async-arrive per producer thread
      MBARRIER_INIT(bar + s * 16 + 8, 16);   // empty: one arrive per consumer warp
    }
  }
  __syncthreads();

  if (tid >= N_CONS) {
    // ---------------- producer: 2 warps ----------------
    const int t = tid - N_CONS;              // 0..63
    const int r0 = t >> 3, c = t & 7;        // rows r0+8j, 16B seg c
    int pst = 0, pph = 1;
#pragma unroll 1
    for (int nc = 0; nc < 4; ++nc) {
      const int n0 = nc * 128;
#pragma unroll 1
      for (int kc = 0; kc < 24; ++kc) {
        MBAR_WAIT(bar + pst * 16 + 8, pph);  // wait stage empty
        const __nv_bfloat16* asrc = ((kc >> 3) == 1) ? slo : shi;
        const int k0 = (kc & 7) << 6;
        const int kg = kc << 6;
        const uint32_t base = sb + pst * SSTRIDE;
        uint32_t ad = base + r0 * APITCH + c * 16;
        const __nv_bfloat16* ap = asrc + (((size_t)(b0 + r0)) << 9) + k0 + c * 8;
        uint32_t bd = base + A_BYTES + r0 * APITCH + c * 16;
        const __nv_bfloat16* bp = Bmat + (size_t)(n0 + r0) * 1536 + kg + c * 8;
#pragma unroll
        for (int j = 0; j < 16; j++) {       // 128 rows each of A and B
          cp16(ad, ap); cp16(bd, bp);
          ad += 8 * APITCH; ap += 8 * 512;
          bd += 8 * APITCH; bp += 8 * 1536;
        }
        CPASYNC_MBAR_ARRIVE(bar + pst * 16); // full arrive when these cp.async land
        if (++pst == NSTG) { pst = 0; pph ^= 1; }
      }
    }
  } else {
    // ---------------- consumer: 16 warps ----------------
    const int lane = tid & 31, wid = tid >> 5;
    const int warp_m = wid & 3;              // 4 warps x 32 rows
    const int warp_n = wid >> 2;             // 4 warps x 32 cols
    const int lr = lane & 15, lc = lane >> 4;
    const uint32_t a_off = (warp_m * 32 + lr) * APITCH + lc * 16;
    const uint32_t b_off = A_BYTES + (warp_n * 32 + lr) * APITCH + lc * 16;
    int cst = 0, cph = 0;

#pragma unroll 1
    for (int nc = 0; nc < 4; ++nc) {
      const int n0 = nc * 128;
      float acc[2][4][4];
#pragma unroll
      for (int i = 0; i < 2; i++)
#pragma unroll
        for (int j = 0; j < 4; j++)
#pragma unroll
          for (int q = 0; q < 4; q++) acc[i][j][q] = 0.f;

#pragma unroll 1
      for (int kc = 0; kc < 24; ++kc) {
        MBAR_WAIT(bar + cst * 16, cph);      // wait stage full
        const uint32_t ab = sb + cst * SSTRIDE + a_off;
        const uint32_t bb = sb + cst * SSTRIDE + b_off;
#pragma unroll
        for (int kk = 0; kk < 4; kk++) {
          uint32_t a[2][4], bfr[2][4];
          LDSM4(a[0][0], a[0][1], a[0][2], a[0][3], ab + kk * 32);
          LDSM4(a[1][0], a[1][1], a[1][2], a[1][3], ab + 16 * APITCH + kk * 32);
          LDSM4(bfr[0][0], bfr[0][1], bfr[0][2], bfr[0][3], bb + kk * 32);
          LDSM4(bfr[1][0], bfr[1][1], bfr[1][2], bfr[1][3], bb + 16 * APITCH + kk * 32);
#pragma unroll
          for (int fm = 0; fm < 2; fm++)
#pragma unroll
            for (int fn = 0; fn < 2; fn++) {
              MMA16816(acc[fm][2 * fn],     a[fm], bfr[fn][0], bfr[fn][2]);
              MMA16816(acc[fm][2 * fn + 1], a[fm], bfr[fn][1], bfr[fn][3]);
            }
        }
        if (lane == 0) MBARRIER_ARRIVE(bar + cst * 16 + 8);  // release stage
        if (++cst == NSTG) { cst = 0; cph ^= 1; }
      }

      // ---- fused epilogue on register fragments (overlaps producer prefetch) ----
      const int rq = lane >> 2, cq = (lane & 3) * 2;
#pragma unroll
      for (int fn = 0; fn < 4; fn++) {
        const int nn = n0 + warp_n * 32 + fn * 8 + cq;
#pragma unroll
        for (int fm = 0; fm < 2; fm++) {
#pragma unroll
          for (int half = 0; half < 2; half++) {
            const int r = b0 + warp_m * 32 + fm * 16 + rq + half * 8;
            const size_t ix = ((size_t)r << 9) + nn;
            const float c0 = acc[fm][fn][half * 2];
            const float c1 = acc[fm][fn][half * 2 + 1];
            if (MODE == 4) {
              float2 bv = *reinterpret_cast<const float2*>(bvec + nn);
              float2 o = make_float2(c0 + bv.x, c1 + bv.y);
              *reinterpret_cast<float2*>(g_drive + ix) = o;
            } else {
              const float2 it2 = *reinterpret_cast<const float2*>(g_itau + nn);
              float2 dr = *reinterpret_cast<const float2*>(g_drive + ix);
              __nv_bfloat162 sh2 = *reinterpret_cast<const __nv_bfloat162*>(shi + ix);
              __nv_bfloat162 sl2 = *reinterpret_cast<const __nv_bfloat162*>(slo + ix);
              float s0 = __bfloat162float(sh2.x) + __bfloat162float(sl2.x);
              float s1 = __bfloat162float(sh2.y) + __bfloat162float(sl2.y);
              float t0 = tanh_fast(c0 + dr.x);
              float t1 = tanh_fast(c1 + dr.y);
              float k0 = (t0 - s0) * it2.x;
              float k1 = (t1 - s1) * it2.y;
              float v0, v1;
              if (MODE == 0) {
                v0 = s0 + HDT * k0; v1 = s1 + HDT * k1;     // s2 = h + dt/2 k1
              } else {
                __nv_bfloat162 hh2 = *reinterpret_cast<const __nv_bfloat162*>(g_S0h + ix);
                __nv_bfloat162 hl2 = *reinterpret_cast<const __nv_bfloat162*>(g_S0l + ix);
                float h0 = __bfloat162float(hh2.x) + __bfloat162float(hl2.x);
                float h1 = __bfloat162float(hh2.y) + __bfloat162float(hl2.y);
                if (MODE == 1)      { v0 = h0 + HDT * k0; v1 = h1 + HDT * k1; }  // s3
                else if (MODE == 2) { v0 = h0 + DT * k0;  v1 = h1 + DT * k1;  }  // s4
                else {
                  __nv_bfloat162 ah2 = *reinterpret_cast<const __nv_bfloat162*>(g_S1h + ix);
                  __nv_bfloat162 al2 = *reinterpret_cast<const __nv_bfloat162*>(g_S1l + ix);
                  __nv_bfloat162 bh2 = *reinterpret_cast<const __nv_bfloat162*>(g_S2h + ix);
                  __nv_bfloat162 bl2 = *reinterpret_cast<const __nv_bfloat162*>(g_S2l + ix);
                  float s20 = __bfloat162float(ah2.x) + __bfloat162float(al2.x);
                  float s21 = __bfloat162float(ah2.y) + __bfloat162float(al2.y);
                  float s30 = __bfloat162float(bh2.x) + __bfloat162float(bl2.x);
                  float s31 = __bfloat162float(bh2.y) + __bfloat162float(bl2.y);
                  v0 = h0 + (1.0f / 3.0f) * (s20 - h0) + (2.0f / 3.0f) * (s30 - h0)
                          + (1.0f / 3.0f) * (s0 - h0) + DT6 * k0;  // h_{n+1}
                  v1 = h1 + (1.0f / 3.0f) * (s21 - h1) + (2.0f / 3.0f) * (s31 - h1)
                          + (1.0f / 3.0f) * (s1 - h1) + DT6 * k1;
                }
              }
              __nv_bfloat16 hi0 = __float2bfloat16(v0);
              __nv_bfloat16 hi1 = __float2bfloat16(v1);
              __nv_bfloat162 oh; oh.x = hi0; oh.y = hi1;
              __nv_bfloat162 ol;
              ol.x = __float2bfloat16(v0 - __bfloat162float(hi0));
              ol.y = __float2bfloat16(v1 - __bfloat162float(hi1));
              *reinterpret_cast<__nv_bfloat162*>(dsth + ix) = oh;
              *reinterpret_cast<__nv_bfloat162*>(dstl + ix) = ol;
            }
          }
        }
      }
    }
  }
}

// ---------------- launcher ----------------
extern "C" void kernel_launch(void* const* d_in, const int* in_sizes, int n_in,
                              void* d_out, int out_size) {
  (void)in_sizes; (void)n_in; (void)out_size;
  const float* x    = (const float*)d_in[0];
  const float* Wx   = (const float*)d_in[1];
  const float* bx   = (const float*)d_in[2];
  const float* W    = (const float*)d_in[3];
  const float* U    = (const float*)d_in[4];
  const float* bvec = (const float*)d_in[5];
  const float* tau  = (const float*)d_in[6];
  const float* Wf   = (const float*)d_in[7];
  const float* bf   = (const float*)d_in[8];
  float* out = (float*)d_out;

  cudaFuncSetAttribute(k_gemm<0>, cudaFuncAttributeMaxDynamicSharedMemorySize, ST_SMEM);
  cudaFuncSetAttribute(k_gemm<1>, cudaFuncAttributeMaxDynamicSharedMemorySize, ST_SMEM);
  cudaFuncSetAttribute(k_gemm<2>, cudaFuncAttributeMaxDynamicSharedMemorySize, ST_SMEM);
  cudaFuncSetAttribute(k_gemm<3>, cudaFuncAttributeMaxDynamicSharedMemorySize, ST_SMEM);
  cudaFuncSetAttribute(k_gemm<4>, cudaFuncAttributeMaxDynamicSharedMemorySize, ST_SMEM);
  cudaFuncSetAttribute(k_head,  cudaFuncAttributeMaxDynamicSharedMemorySize, 65536);
  cudaFuncSetAttribute(k_in,    cudaFuncAttributeMaxDynamicSharedMemorySize, 32768);

  k_prep<<<(2 * 512 * 1536) / 256, 256>>>(W, U, tau);
  k_in<<<BATCH / 32, 256, 32768>>>(x, Wx, bx);
  k_gemm<4><<<BATCH / 128, NTHR, ST_SMEM>>>(bvec);       // drive
  for (int step = 0; step < NSTEPS; ++step) {
    k_gemm<0><<<BATCH / 128, NTHR, ST_SMEM>>>(nullptr);
    k_gemm<1><<<BATCH / 128, NTHR, ST_SMEM>>>(nullptr);
    k_gemm<2><<<BATCH / 128, NTHR, ST_SMEM>>>(nullptr);
    k_gemm<3><<<BATCH / 128, NTHR, ST_SMEM>>>(nullptr);
  }
  k_head<<<BATCH / 32, 256, 65536>>>(Wf, bf, out);
}

// round 10
// speedup vs baseline: 5.4457x; 1.2367x over previous
#include <cuda_runtime.h>
#include <cuda_fp16.h>
#include <cstdint>

#define BATCH    32768
#define IN_DIM   256
#define HID      512
#define OUT_DIM  128
#define NSTEPS   40
#define DT       0.025f
#define HDT      0.0125f
#define DT6      (0.025f / 6.0f)
#define KP       1024            /* K' = 2 * HID (fp16 2-term split) */

// ---------------- static device scratch ----------------
__device__ __align__(128) __half g_S0h[(size_t)BATCH * HID];
__device__ __align__(128) __half g_S0l[(size_t)BATCH * HID];
__device__ __align__(128) __half g_S1h[(size_t)BATCH * HID];
__device__ __align__(128) __half g_S1l[(size_t)BATCH * HID];
__device__ __align__(128) __half g_S2h[(size_t)BATCH * HID];
__device__ __align__(128) __half g_S2l[(size_t)BATCH * HID];
__device__ __align__(128) __half g_S3h[(size_t)BATCH * HID];
__device__ __align__(128) __half g_S3l[(size_t)BATCH * HID];
__device__ __align__(128) __half g_Wbig[(size_t)HID * KP];   // [n][k']: Wf16 | Wf16
__device__ __align__(128) __half g_Ubig[(size_t)HID * KP];   // [n][k']: Uf16 | Uf16
__device__ __align__(128) float g_drive[(size_t)BATCH * HID];
__device__ __align__(128) float g_itau[HID];

__device__ __forceinline__ __half* Sh_ptr(int i) {
  switch (i) { case 0: return g_S0h; case 1: return g_S1h; case 2: return g_S2h; default: return g_S3h; }
}
__device__ __forceinline__ __half* Sl_ptr(int i) {
  switch (i) { case 0: return g_S0l; case 1: return g_S1l; case 2: return g_S2l; default: return g_S3l; }
}

// ---------------- helpers ----------------
__device__ __forceinline__ uint32_t smem_u32(const void* p) {
  uint32_t a;
  asm("{ .reg .u64 t; cvta.to.shared.u64 t, %1; cvt.u32.u64 %0, t; }" : "=r"(a) : "l"(p));
  return a;
}
__device__ __forceinline__ void cp16(uint32_t dst, const void* src) {
  asm volatile("cp.async.cg.shared.global [%0], [%1], 16;" :: "r"(dst), "l"(src) : "memory");
}
#define MBARRIER_INIT(a, c) \
  asm volatile("mbarrier.init.shared.b64 [%0], %1;" :: "r"(a), "r"((uint32_t)(c)) : "memory")
#define MBARRIER_ARRIVE(a) \
  asm volatile("mbarrier.arrive.shared.b64 _, [%0];" :: "r"(a) : "memory")
#define CPASYNC_MBAR_ARRIVE(a) \
  asm volatile("cp.async.mbarrier.arrive.noinc.shared::cta.b64 [%0];" :: "r"(a) : "memory")
#define MBAR_WAIT(a, ph) do {                                              \
  uint32_t _m = (a), _p = (uint32_t)(ph), _d;                              \
  asm volatile("{ .reg .pred p; mbarrier.try_wait.parity.acquire.cta.shared::cta.b64 p, [%1], %2; selp.b32 %0,1,0,p; }" \
               : "=r"(_d) : "r"(_m), "r"(_p) : "memory");                  \
  if (!_d) {                                                               \
    asm volatile("{ .reg .pred P1; WL%=: mbarrier.try_wait.parity.acquire.cta.shared::cta.b64 P1, [%0], %1, 0x989680; @P1 bra.uni WD%=; bra.uni WL%=; WD%=: }" \
                 :: "r"(_m), "r"(_p) : "memory");                          \
  }                                                                        \
} while (0)

#define LDSM4(r0, r1, r2, r3, a) \
  asm volatile("ldmatrix.sync.aligned.m8n8.x4.shared.b16 {%0,%1,%2,%3}, [%4];" \
               : "=r"(r0), "=r"(r1), "=r"(r2), "=r"(r3) : "r"(a))

#define MMA16816(d, a, b0, b1) \
  asm volatile("mma.sync.aligned.m16n8k16.row.col.f32.f16.f16.f32 " \
               "{%0,%1,%2,%3},{%4,%5,%6,%7},{%8,%9},{%0,%1,%2,%3};" \
               : "+f"((d)[0]), "+f"((d)[1]), "+f"((d)[2]), "+f"((d)[3]) \
               : "r"((a)[0]), "r"((a)[1]), "r"((a)[2]), "r"((a)[3]), "r"(b0), "r"(b1))

__device__ __forceinline__ float tanh_fast(float x) {
  float e = __expf(2.0f * x);
  return 1.0f - __fdividef(2.0f, e + 1.0f);
}

// ---------------- prep: W/U -> [f16 | f16] duplicated, itau ----------------
__global__ void k_prep(const float* __restrict__ W, const float* __restrict__ U,
                       const float* __restrict__ tau) {
  int idx = blockIdx.x * 256 + threadIdx.x;           // 2*512*1024 total
  const int HALF = HID * KP;
  int h = (idx >= HALF) ? 1 : 0;
  int j = idx - h * HALF;
  int n = j >> 10, k = j & (KP - 1);
  int kk = k & 511;
  const float* src = h ? U : W;
  __half* dst = h ? g_Ubig : g_Wbig;
  dst[j] = __float2half(src[n * 512 + kk]);
  if (idx < HID) g_itau[idx] = 1.0f / tau[idx];
}

// ---------------- fp32 microtile GEMM (k_in / k_head) ----------------
template <int K>
__device__ __forceinline__ void gemm_tile(const float* __restrict__ As,
                                          const float* __restrict__ Bg,
                                          int row0, int col0, float acc[4][16]) {
#pragma unroll
  for (int i = 0; i < 4; i++)
#pragma unroll
    for (int j = 0; j < 16; j++) acc[i][j] = 0.f;
#pragma unroll 1
  for (int k = 0; k < K; k += 4) {
    float4 a[4];
#pragma unroll
    for (int kk = 0; kk < 4; kk++)
      a[kk] = *reinterpret_cast<const float4*>(As + (k + kk) * 32 + row0);
    float4 bb[16];
#pragma unroll
    for (int j = 0; j < 16; j++)
      bb[j] = *reinterpret_cast<const float4*>(Bg + (size_t)(col0 + j) * K + k);
#pragma unroll
    for (int j = 0; j < 16; j++) {
      float bv[4] = {bb[j].x, bb[j].y, bb[j].z, bb[j].w};
#pragma unroll
      for (int kk = 0; kk < 4; kk++) {
        acc[0][j] = fmaf(a[kk].x, bv[kk], acc[0][j]);
        acc[1][j] = fmaf(a[kk].y, bv[kk], acc[1][j]);
        acc[2][j] = fmaf(a[kk].z, bv[kk], acc[2][j]);
        acc[3][j] = fmaf(a[kk].w, bv[kk], acc[3][j]);
      }
    }
  }
}

// u = x @ Wx^T + bx ; writes S0 (h0 = u) as fp16 hi/lo
__global__ void __launch_bounds__(256, 1)
k_in(const float* __restrict__ x, const float* __restrict__ Wx,
     const float* __restrict__ bx) {
  extern __shared__ float sm[];
  const int tid = threadIdx.x, b0 = blockIdx.x * 32;
  for (int idx = tid; idx < 32 * IN_DIM; idx += 256) {
    int m = idx >> 8, k = idx & 255;
    sm[k * 32 + m] = x[(size_t)(b0 + m) * IN_DIM + k];
  }
  __syncthreads();
  const int row0 = (tid & 7) * 4, col0 = (tid >> 3) * 16;
  float acc[4][16];
  gemm_tile<IN_DIM>(sm, Wx, row0, col0, acc);
#pragma unroll
  for (int j = 0; j < 16; j++) {
    float bxi = bx[col0 + j];
#pragma unroll
    for (int i = 0; i < 4; i++) {
      float v = acc[i][j] + bxi;
      size_t ix = (size_t)(b0 + row0 + i) * HID + col0 + j;
      __half hi = __float2half(v);
      g_S0h[ix] = hi;
      g_S0l[ix] = __float2half(v - __half2float(hi));
    }
  }
}

// out = h @ Wf^T + bf  (h = S0 hi+lo)
__global__ void __launch_bounds__(256, 1)
k_head(const float* __restrict__ Wf, const float* __restrict__ bf,
       float* __restrict__ out) {
  extern __shared__ float sm[];
  const int tid = threadIdx.x, b0 = blockIdx.x * 32;
  for (int idx = tid; idx < 32 * HID; idx += 256) {
    int m = idx >> 9, k = idx & 511;
    size_t ix = (size_t)(b0 + m) * HID + k;
    sm[k * 32 + m] = __half2float(g_S0h[ix]) + __half2float(g_S0l[ix]);
  }
  __syncthreads();
  const int row0 = (tid & 7) * 4, oc0 = (tid >> 3) * 4;
  float acc[4][4];
#pragma unroll
  for (int i = 0; i < 4; i++)
#pragma unroll
    for (int j = 0; j < 4; j++) acc[i][j] = 0.f;
#pragma unroll 1
  for (int k = 0; k < HID; k += 4) {
    float4 a[4];
#pragma unroll
    for (int kk = 0; kk < 4; kk++)
      a[kk] = *reinterpret_cast<const float4*>(sm + (k + kk) * 32 + row0);
#pragma unroll
    for (int j = 0; j < 4; j++) {
      float4 bb = *reinterpret_cast<const float4*>(Wf + (size_t)(oc0 + j) * HID + k);
      float bv[4] = {bb.x, bb.y, bb.z, bb.w};
#pragma unroll
      for (int kk = 0; kk < 4; kk++) {
        acc[0][j] = fmaf(a[kk].x, bv[kk], acc[0][j]);
        acc[1][j] = fmaf(a[kk].y, bv[kk], acc[1][j]);
        acc[2][j] = fmaf(a[kk].z, bv[kk], acc[2][j]);
        acc[3][j] = fmaf(a[kk].w, bv[kk], acc[3][j]);
      }
    }
  }
#pragma unroll
  for (int i = 0; i < 4; i++) {
    float4 o = make_float4(acc[i][0] + bf[oc0 + 0], acc[i][1] + bf[oc0 + 1],
                           acc[i][2] + bf[oc0 + 2], acc[i][3] + bf[oc0 + 3]);
    *reinterpret_cast<float4*>(out + (size_t)(b0 + row0 + i) * OUT_DIM + oc0) = o;
  }
}

// ---------------- warp-specialized HMMA GEMM kernel (fp16, K'=1024) ----------
// MODE 0..3: RK4 stage. MODE 4: drive = u @ U^T + b.
// 576 threads: 16 consumer warps (4M x 4N, 32x32 tiles, 128 rows x 128 cols/nc,
// 4 n-chunks) + 2 producer warps streaming a 4-stage cp.async ring.
// K chunk = 64 (16 chunks/nc, 64 chunks total). mbarrier full/empty per stage.
#define APITCH     144
#define A_BYTES    18432          /* 128*144 */
#define SSTRIDE    36864          /* A + B per stage */
#define NSTG       4
#define RING_BYTES (NSTG * SSTRIDE)
#define ST_SMEM    (RING_BYTES + 128)
#define N_CONS     512
#define N_PROD     64
#define NTHR       (N_CONS + N_PROD)
#define NCHUNK     16             /* K'=1024 / 64 */

template <int MODE>
__global__ void __launch_bounds__(NTHR, 1) k_gemm(const float* __restrict__ bvec) {
  extern __shared__ __align__(128) char smem[];
  const uint32_t sb = smem_u32(smem);
  const uint32_t bar = sb + RING_BYTES;      // full[s]@bar+16s, empty[s]@bar+16s+8
  const int tid = threadIdx.x;
  const int b0 = blockIdx.x * 128;

  const __half* shi = (MODE == 4) ? g_S0h : Sh_ptr(MODE);
  const __half* slo = (MODE == 4) ? g_S0l : Sl_ptr(MODE);
  const __half* Bmat = (MODE == 4) ? g_Ubig : g_Wbig;
  __half* dsth = (MODE == 4) ? g_S0h : Sh_ptr((MODE + 1) & 3);
  __half* dstl = (MODE == 4) ? g_S0l : Sl_ptr((MODE + 1) & 3);

  if (tid == 0) {
#pragma unroll
    for (int s = 0; s < NSTG; s++) {
      MBARRIER_INIT(bar + s * 16, N_PROD);   // full: cp.async-arrive per producer thread
      MBARRIER_INIT(bar + s * 16 + 8, 16);   // empty: one arrive per consumer warp
    }
  }
  __syncthreads();

  if (tid >= N_CONS) {
    // ---------------- producer: 2 warps ----------------
    const int t = tid - N_CONS;              // 0..63
    const int r0 = t >> 3, c = t & 7;        // rows r0+8j, 16B seg c
    int pst = 0, pph = 1;
#pragma unroll 1
    for (int nc = 0; nc < 4; ++nc) {
      const int n0 = nc * 128;
#pragma unroll 1
      for (int kc = 0; kc < NCHUNK; ++kc) {
        MBAR_WAIT(bar + pst * 16 + 8, pph);  // wait stage empty
        const __half* asrc = (kc >= 8) ? slo : shi;
        const int k0 = (kc & 7) << 6;
        const int kg = kc << 6;
        const uint32_t base = sb + pst * SSTRIDE;
        uint32_t ad = base + r0 * APITCH + c * 16;
        const __half* ap = asrc + (((size_t)(b0 + r0)) << 9) + k0 + c * 8;
        uint32_t bd = base + A_BYTES + r0 * APITCH + c * 16;
        const __half* bp = Bmat + ((size_t)(n0 + r0) << 10) + kg + c * 8;
#pragma unroll
        for (int j = 0; j < 16; j++) {       // 128 rows each of A and B
          cp16(ad, ap); cp16(bd, bp);
          ad += 8 * APITCH; ap += 8 * 512;
          bd += 8 * APITCH; bp += 8 * 1024;
        }
        CPASYNC_MBAR_ARRIVE(bar + pst * 16); // full arrive when these cp.async land
        if (++pst == NSTG) { pst = 0; pph ^= 1; }
      }
    }
  } else {
    // ---------------- consumer: 16 warps ----------------
    const int lane = tid & 31, wid = tid >> 5;
    const int warp_m = wid & 3;              // 4 warps x 32 rows
    const int warp_n = wid >> 2;             // 4 warps x 32 cols
    const int lr = lane & 15, lc = lane >> 4;
    const uint32_t a_off = (warp_m * 32 + lr) * APITCH + lc * 16;
    const uint32_t b_off = A_BYTES + (warp_n * 32 + lr) * APITCH + lc * 16;
    int cst = 0, cph = 0;

#pragma unroll 1
    for (int nc = 0; nc < 4; ++nc) {
      const int n0 = nc * 128;
      float acc[2][4][4];
#pragma unroll
      for (int i = 0; i < 2; i++)
#pragma unroll
        for (int j = 0; j < 4; j++)
#pragma unroll
          for (int q = 0; q < 4; q++) acc[i][j][q] = 0.f;

#pragma unroll 1
      for (int kc = 0; kc < NCHUNK; ++kc) {
        MBAR_WAIT(bar + cst * 16, cph);      // wait stage full
        const uint32_t ab = sb + cst * SSTRIDE + a_off;
        const uint32_t bb = sb + cst * SSTRIDE + b_off;
#pragma unroll
        for (int kk = 0; kk < 4; kk++) {
          uint32_t a[2][4], bfr[2][4];
          LDSM4(a[0][0], a[0][1], a[0][2], a[0][3], ab + kk * 32);
          LDSM4(a[1][0], a[1][1], a[1][2], a[1][3], ab + 16 * APITCH + kk * 32);
          LDSM4(bfr[0][0], bfr[0][1], bfr[0][2], bfr[0][3], bb + kk * 32);
          LDSM4(bfr[1][0], bfr[1][1], bfr[1][2], bfr[1][3], bb + 16 * APITCH + kk * 32);
#pragma unroll
          for (int fm = 0; fm < 2; fm++)
#pragma unroll
            for (int fn = 0; fn < 2; fn++) {
              MMA16816(acc[fm][2 * fn],     a[fm], bfr[fn][0], bfr[fn][2]);
              MMA16816(acc[fm][2 * fn + 1], a[fm], bfr[fn][1], bfr[fn][3]);
            }
        }
        if (lane == 0) MBARRIER_ARRIVE(bar + cst * 16 + 8);  // release stage
        if (++cst == NSTG) { cst = 0; cph ^= 1; }
      }

      // ---- fused epilogue on register fragments (overlaps producer prefetch) ----
      const int rq = lane >> 2, cq = (lane & 3) * 2;
#pragma unroll
      for (int fn = 0; fn < 4; fn++) {
        const int nn = n0 + warp_n * 32 + fn * 8 + cq;
#pragma unroll
        for (int fm = 0; fm < 2; fm++) {
#pragma unroll
          for (int half = 0; half < 2; half++) {
            const int r = b0 + warp_m * 32 + fm * 16 + rq + half * 8;
            const size_t ix = ((size_t)r << 9) + nn;
            const float c0 = acc[fm][fn][half * 2];
            const float c1 = acc[fm][fn][half * 2 + 1];
            if (MODE == 4) {
              float2 bv = *reinterpret_cast<const float2*>(bvec + nn);
              float2 o = make_float2(c0 + bv.x, c1 + bv.y);
              *reinterpret_cast<float2*>(g_drive + ix) = o;
            } else {
              const float2 it2 = *reinterpret_cast<const float2*>(g_itau + nn);
              float2 dr = *reinterpret_cast<const float2*>(g_drive + ix);
              float2 shf = __half22float2(*reinterpret_cast<const __half2*>(shi + ix));
              float2 slf = __half22float2(*reinterpret_cast<const __half2*>(slo + ix));
              float s0 = shf.x + slf.x;
              float s1 = shf.y + slf.y;
              float t0 = tanh_fast(c0 + dr.x);
              float t1 = tanh_fast(c1 + dr.y);
              float k0 = (t0 - s0) * it2.x;
              float k1 = (t1 - s1) * it2.y;
              float v0, v1;
              if (MODE == 0) {
                v0 = s0 + HDT * k0; v1 = s1 + HDT * k1;     // s2 = h + dt/2 k1
              } else {
                float2 hhf = __half22float2(*reinterpret_cast<const __half2*>(g_S0h + ix));
                float2 hlf = __half22float2(*reinterpret_cast<const __half2*>(g_S0l + ix));
                float h0 = hhf.x + hlf.x;
                float h1 = hhf.y + hlf.y;
                if (MODE == 1)      { v0 = h0 + HDT * k0; v1 = h1 + HDT * k1; }  // s3
                else if (MODE == 2) { v0 = h0 + DT * k0;  v1 = h1 + DT * k1;  }  // s4
                else {
                  float2 a2 = __half22float2(*reinterpret_cast<const __half2*>(g_S1h + ix));
                  float2 a2l = __half22float2(*reinterpret_cast<const __half2*>(g_S1l + ix));
                  float2 b2 = __half22float2(*reinterpret_cast<const __half2*>(g_S2h + ix));
                  float2 b2l = __half22float2(*reinterpret_cast<const __half2*>(g_S2l + ix));
                  float s20 = a2.x + a2l.x, s21 = a2.y + a2l.y;
                  float s30 = b2.x + b2l.x, s31 = b2.y + b2l.y;
                  v0 = h0 + (1.0f / 3.0f) * (s20 - h0) + (2.0f / 3.0f) * (s30 - h0)
                          + (1.0f / 3.0f) * (s0 - h0) + DT6 * k0;  // h_{n+1}
                  v1 = h1 + (1.0f / 3.0f) * (s21 - h1) + (2.0f / 3.0f) * (s31 - h1)
                          + (1.0f / 3.0f) * (s1 - h1) + DT6 * k1;
                }
              }
              __half hi0 = __float2half(v0);
              __half hi1 = __float2half(v1);
              __half2 oh; oh.x = hi0; oh.y = hi1;
              __half2 ol;
              ol.x = __float2half(v0 - __half2float(hi0));
              ol.y = __float2half(v1 - __half2float(hi1));
              *reinterpret_cast<__half2*>(dsth + ix) = oh;
              *reinterpret_cast<__half2*>(dstl + ix) = ol;
            }
          }
        }
      }
    }
  }
}

// ---------------- launcher ----------------
extern "C" void kernel_launch(void* const* d_in, const int* in_sizes, int n_in,
                              void* d_out, int out_size) {
  (void)in_sizes; (void)n_in; (void)out_size;
  const float* x    = (const float*)d_in[0];
  const float* Wx   = (const float*)d_in[1];
  const float* bx   = (const float*)d_in[2];
  const float* W    = (const float*)d_in[3];
  const float* U    = (const float*)d_in[4];
  const float* bvec = (const float*)d_in[5];
  const float* tau  = (const float*)d_in[6];
  const float* Wf   = (const float*)d_in[7];
  const float* bf   = (const float*)d_in[8];
  float* out = (float*)d_out;

  cudaFuncSetAttribute(k_gemm<0>, cudaFuncAttributeMaxDynamicSharedMemorySize, ST_SMEM);
  cudaFuncSetAttribute(k_gemm<1>, cudaFuncAttributeMaxDynamicSharedMemorySize, ST_SMEM);
  cudaFuncSetAttribute(k_gemm<2>, cudaFuncAttributeMaxDynamicSharedMemorySize, ST_SMEM);
  cudaFuncSetAttribute(k_gemm<3>, cudaFuncAttributeMaxDynamicSharedMemorySize, ST_SMEM);
  cudaFuncSetAttribute(k_gemm<4>, cudaFuncAttributeMaxDynamicSharedMemorySize, ST_SMEM);
  cudaFuncSetAttribute(k_head,  cudaFuncAttributeMaxDynamicSharedMemorySize, 65536);
  cudaFuncSetAttribute(k_in,    cudaFuncAttributeMaxDynamicSharedMemorySize, 32768);

  k_prep<<<(2 * HID * KP) / 256, 256>>>(W, U, tau);
  k_in<<<BATCH / 32, 256, 32768>>>(x, Wx, bx);
  k_gemm<4><<<BATCH / 128, NTHR, ST_SMEM>>>(bvec);       // drive
  for (int step = 0; step < NSTEPS; ++step) {
    k_gemm<0><<<BATCH / 128, NTHR, ST_SMEM>>>(nullptr);
    k_gemm<1><<<BATCH / 128, NTHR, ST_SMEM>>>(nullptr);
    k_gemm<2><<<BATCH / 128, NTHR, ST_SMEM>>>(nullptr);
    k_gemm<3><<<BATCH / 128, NTHR, ST_SMEM>>>(nullptr);
  }
  k_head<<<BATCH / 32, 256, 65536>>>(Wf, bf, out);
}